// round 5
// baseline (speedup 1.0000x reference)
#include <cuda_runtime.h>

// WindowEmbedding forward: out[b, t, k*D + d] = (t-k >= 0) ? in[b, t-k, d] : 0
// B=16, T=2048, D=256, W=7.
// R4: smem staging (keeps L2 under its cap) + plain stores (let L2 batch dirty
// writebacks instead of __stcs evict-first write-through) + batch-4 LDS->STG
// pipelining so stores don't chain on 29-cycle LDS latency.

#define B_DIM 16
#define T_DIM 2048
#define D_DIM 256
#define W_DIM 7

#define D4 (D_DIM / 4)            // 64 float4 per input row
#define SLICE4 (W_DIM * D4)       // 448 float4 per output row
#define TILE_T 16                 // t-values per block
#define HALO (W_DIM - 1)          // 6
#define ROWS (TILE_T + HALO)      // 22 staged rows
#define NTHREADS SLICE4           // 448
#define BATCH 4

__global__ __launch_bounds__(NTHREADS) void window_embed_kernel(
    const float4* __restrict__ in,   // [B, T, 64] float4
    float4* __restrict__ out)        // [B, T, 448] float4
{
    __shared__ float4 s[ROWS * D4];  // 22 KB

    const int bt0 = blockIdx.x * TILE_T;     // b*T + t0, t0 multiple of 16
    const int t0  = bt0 & (T_DIM - 1);
    const int tid = threadIdx.x;             // 0..447

    // Stage rows (t0-6 .. t0+15) into smem, zero-filling t < 0.
    const float4 zero = make_float4(0.f, 0.f, 0.f, 0.f);
    #pragma unroll
    for (int i = tid; i < ROWS * D4; i += NTHREADS) {
        const int r  = i >> 6;
        const int ts = t0 - HALO + r;
        s[i] = (ts >= 0) ? in[(long long)(bt0 - HALO + r) * D4 + (i & 63)]
                         : zero;
    }
    __syncthreads();

    // Fan out: out[t0+j][k*64 + d4] = s[(j + 6 - k)*64 + d4]
    const int k  = tid >> 6;                 // shift 0..6
    const int d4 = tid & 63;
    const float4* srow = &s[(HALO - k) * D4 + d4];
    float4* dst = out + (long long)bt0 * SLICE4 + tid;

    #pragma unroll
    for (int jb = 0; jb < TILE_T; jb += BATCH) {
        float4 v[BATCH];
        #pragma unroll
        for (int j = 0; j < BATCH; j++)
            v[j] = srow[(jb + j) * D4];
        #pragma unroll
        for (int j = 0; j < BATCH; j++)
            dst[(jb + j) * SLICE4] = v[j];
    }
}

extern "C" void kernel_launch(void* const* d_in, const int* in_sizes, int n_in,
                              void* d_out, int out_size)
{
    const float4* in = (const float4*)d_in[0];
    float4* out = (float4*)d_out;

    dim3 grid(B_DIM * T_DIM / TILE_T);   // 2048
    dim3 block(NTHREADS);                // 448
    window_embed_kernel<<<grid, block>>>(in, out);
}

// round 6
// speedup vs baseline: 1.0946x; 1.0946x over previous
#include <cuda_runtime.h>

// WindowEmbedding forward: out[b, t, k*D + d] = (t-k >= 0) ? in[b, t-k, d] : 0
// B=16, T=2048, D=256, W=7.
// R5: revert to R2 structure (fastest measured kernel: direct loads, MLP=8,
// __stcs streaming stores). Three structurally different kernels all plateaued
// at ~40us / DRAM~65% => pure-write DRAM ceiling (~5.2 TB/s for a write-only
// stream). This round recovers the best-known structure and trims the
// boundary predicate path; expectation is roofline-limited.

#define B_DIM 16
#define T_DIM 2048
#define D_DIM 256
#define W_DIM 7

#define D4 (D_DIM / 4)          // 64 float4 per input row
#define SLICE4 (W_DIM * D4)     // 448 float4 per output row
#define TILE_T 8                // t-values per thread

__global__ __launch_bounds__(SLICE4) void window_embed_kernel(
    const float4* __restrict__ in,   // [B, T, 64] float4
    float4* __restrict__ out)        // [B, T, 448] float4
{
    const int bt0 = blockIdx.x * TILE_T;     // base (b*T + t0), t0 multiple of 8
    const int t0  = bt0 & (T_DIM - 1);
    const int tid = threadIdx.x;             // 0..447
    const int k   = tid >> 6;                // shift 0..6
    const int d4  = tid & 63;                // float4 column

    const float4* src = in  + (long long)(bt0 - k) * D4 + d4;
    float4*       dst = out + (long long)bt0 * SLICE4 + tid;

    float4 v[TILE_T];

    if (t0 != 0) {
        // Fast path (4080/4096 blocks): t0 >= 8 > k, all sources valid.
        #pragma unroll
        for (int j = 0; j < TILE_T; j++)
            v[j] = src[j * D4];
        #pragma unroll
        for (int j = 0; j < TILE_T; j++)
            __stcs(&dst[j * SLICE4], v[j]);
    } else {
        // t0 == 0: zero-fill where t - k < 0.
        #pragma unroll
        for (int j = 0; j < TILE_T; j++) {
            const int ts = j - k;
            v[j] = (ts >= 0) ? src[j * D4] : make_float4(0.f, 0.f, 0.f, 0.f);
        }
        #pragma unroll
        for (int j = 0; j < TILE_T; j++)
            __stcs(&dst[j * SLICE4], v[j]);
    }
}

extern "C" void kernel_launch(void* const* d_in, const int* in_sizes, int n_in,
                              void* d_out, int out_size)
{
    const float4* in = (const float4*)d_in[0];
    float4* out = (float4*)d_out;

    dim3 grid(B_DIM * T_DIM / TILE_T);   // 4096
    dim3 block(SLICE4);                  // 448
    window_embed_kernel<<<grid, block>>>(in, out);
}